// round 7
// baseline (speedup 1.0000x reference)
#include <cuda_runtime.h>
#include <cstdint>

// TtLlamaRotary: out[n,s,:] = x[n,s,:] @ R[s,:,:]
//   xq  [8,128,128], xk [1,128,128], rot [128,128,128], out = concat (9,128,128)
//
// Grid (128 s, 4 d-quarters, 2 row-groups {rows 0-4, rows 5-8}).
// Block 128 = 16 h-groups x 8 threads; thread owns 4 output columns.
// R slice (8 x float4) prefetched into registers before the x-staging barrier.
// Row split gives 1024 CTAs x 128 thr = 131K threads (~43% occ) for latency
// hiding; outputs are disjoint so no atomics. Second R read hits L2.

#define SEQ_LEN 128
#define HEAD_DIM 128
#define NQ 8
#define DTILE 32
#define TPG 8
#define NGROUPS 16
#define HCHUNK 8
#define NTHREADS 128
#define NR_MAX 5

template <int NR, int ROW0>
__device__ __forceinline__ void rotary_body(
    float2 (*xs2)[HEAD_DIM], float (*part)[NR_MAX][DTILE],
    const float* __restrict__ xq, const float* __restrict__ xk,
    const float* __restrict__ rot, float* __restrict__ out,
    int s, int dq, int tid)
{
    const int g = tid / TPG;     // h-group 0..15
    const int t = tid % TPG;     // 4-col slot 0..7

    // ---- Prefetch R slice into registers (overlaps x staging) ----
    const float4* __restrict__ R4 =
        (const float4*)rot + (size_t)s * (HEAD_DIM * HEAD_DIM / 4) + dq * (DTILE / 4) + t;
    float4 rv[HCHUNK];
    #pragma unroll
    for (int h = 0; h < HCHUNK; h++)
        rv[h] = R4[(size_t)(g * HCHUNK + h) * (HEAD_DIM / 4)];

    // ---- Stage this row-group's x rows (float4), duplicated float2 ----
    // NR rows x 32 float4 chunks over 128 threads.
    for (int idx = tid; idx < NR * (HEAD_DIM / 4); idx += NTHREADS) {
        const int nl = idx >> 5;          // local row
        const int c  = idx & 31;          // float4 chunk
        const int n  = ROW0 + nl;         // global row
        const float4 v = (n < NQ)
            ? *(const float4*)(xq + ((size_t)(n * SEQ_LEN + s) * HEAD_DIM) + c * 4)
            : *(const float4*)(xk + ((size_t)s * HEAD_DIM) + c * 4);
        xs2[nl][c * 4 + 0] = make_float2(v.x, v.x);
        xs2[nl][c * 4 + 1] = make_float2(v.y, v.y);
        xs2[nl][c * 4 + 2] = make_float2(v.z, v.z);
        xs2[nl][c * 4 + 3] = make_float2(v.w, v.w);
    }
    __syncthreads();

    // ---- Accumulate: 8 h-steps x NR rows, packed f32x2 ----
    unsigned long long acc01[NR], acc23[NR];
    #pragma unroll
    for (int n = 0; n < NR; n++) { acc01[n] = 0ull; acc23[n] = 0ull; }

    #pragma unroll
    for (int h = 0; h < HCHUNK; h++) {
        const int hh = g * HCHUNK + h;
        unsigned long long r01, r23;
        asm("mov.b64 %0, {%1, %2};" : "=l"(r01) : "f"(rv[h].x), "f"(rv[h].y));
        asm("mov.b64 %0, {%1, %2};" : "=l"(r23) : "f"(rv[h].z), "f"(rv[h].w));
        #pragma unroll
        for (int n = 0; n < NR; n++) {
            const unsigned long long x2 =
                *(const unsigned long long*)&xs2[n][hh];   // LDS.64 broadcast
            asm("fma.rn.f32x2 %0, %1, %2, %0;" : "+l"(acc01[n]) : "l"(x2), "l"(r01));
            asm("fma.rn.f32x2 %0, %1, %2, %0;" : "+l"(acc23[n]) : "l"(x2), "l"(r23));
        }
    }

    // ---- Write partials (STS.128) ----
    #pragma unroll
    for (int n = 0; n < NR; n++) {
        float a0, a1, a2, a3;
        asm("mov.b64 {%0, %1}, %2;" : "=f"(a0), "=f"(a1) : "l"(acc01[n]));
        asm("mov.b64 {%0, %1}, %2;" : "=f"(a2), "=f"(a3) : "l"(acc23[n]));
        *(float4*)&part[g][n][t * 4] = make_float4(a0, a1, a2, a3);
    }
    __syncthreads();

    // ---- Reduce 16 partials: NR rows x 8 float4-chunks ----
    if (tid < NR * (DTILE / 4)) {
        const int nl = tid / (DTILE / 4);
        const int c  = tid % (DTILE / 4);
        float4 v = make_float4(0.f, 0.f, 0.f, 0.f);
        #pragma unroll
        for (int gg = 0; gg < NGROUPS; gg++) {
            const float4 p = *(const float4*)&part[gg][nl][c * 4];
            v.x += p.x; v.y += p.y; v.z += p.z; v.w += p.w;
        }
        const int n = ROW0 + nl;   // n==8 lands exactly at the xk block
        const size_t o = (size_t)(n * SEQ_LEN + s) * HEAD_DIM + dq * DTILE + c * 4;
        *(float4*)(out + o) = v;
    }
}

__global__ __launch_bounds__(NTHREADS, 7)
void rotary_kernel(const float* __restrict__ xq,
                   const float* __restrict__ xk,
                   const float* __restrict__ rot,
                   float* __restrict__ out) {
    __shared__ float2 xs2[NR_MAX][HEAD_DIM];
    __shared__ float  part[NGROUPS][NR_MAX][DTILE];

    const int s   = blockIdx.x;
    const int dq  = blockIdx.y;
    const int tid = threadIdx.x;

    if (blockIdx.z == 0)
        rotary_body<5, 0>(xs2, part, xq, xk, rot, out, s, dq, tid);
    else
        rotary_body<4, 5>(xs2, part, xq, xk, rot, out, s, dq, tid);
}

extern "C" void kernel_launch(void* const* d_in, const int* in_sizes, int n_in,
                              void* d_out, int out_size) {
    const float* xq  = (const float*)d_in[0];
    const float* xk  = (const float*)d_in[1];
    const float* rot = (const float*)d_in[2];
    float* out = (float*)d_out;

    dim3 grid(SEQ_LEN, 4, 2);
    rotary_kernel<<<grid, NTHREADS>>>(xq, xk, rot, out);
}

// round 8
// speedup vs baseline: 1.0895x; 1.0895x over previous
#include <cuda_runtime.h>
#include <cstdint>

// TtLlamaRotary: out[n,s,:] = x[n,s,:] @ R[s,:,:]
//   xq [8,128,128], xk [1,128,128], rot [128,128,128], out concat (9,128,128)
//
// One CTA per seq position s (grid 128, block 256 = 8 warp-groups x 32 thr).
// R_s (64 KB, contiguous) streamed into smem by 4x16KB cp.async.bulk (TMA
// engine, no warp-LDG trickle), mbarrier per stage. Warp-group g consumes
// stage g/2 -> compute overlaps streaming. x staged via LDG concurrently.
// f32x2 packed accumulation, smem partials, float4 stores.

#define SEQ_LEN 128
#define HEAD_DIM 128
#define NQ 8
#define NROWS 9
#define NGROUPS 8
#define TPG 32
#define HCHUNK 16            // h rows per group
#define NTHREADS 256
#define NSTAGES 4
#define STAGE_BYTES 16384    // 32 h-rows x 512 B

// dynamic smem layout (bytes)
#define SM_MBAR   0                       // 4 x 8B
#define SM_R      1024                    // 65536
#define SM_X      (SM_R + 65536)          // 9*128*8 = 9216 (duplicated float2)
#define SM_PART   (SM_X + 9216)           // 8*9*128*4 = 36864
#define SM_TOTAL  (SM_PART + 36864)       // 112640

__device__ __forceinline__ void mbar_init(uint32_t a, uint32_t cnt) {
    asm volatile("mbarrier.init.shared.b64 [%0], %1;" :: "r"(a), "r"(cnt) : "memory");
}
__device__ __forceinline__ void mbar_expect_tx(uint32_t a, uint32_t bytes) {
    asm volatile("mbarrier.arrive.expect_tx.shared.b64 _, [%0], %1;"
                 :: "r"(a), "r"(bytes) : "memory");
}
__device__ __forceinline__ void bulk_g2s(uint32_t dst, const void* src,
                                         uint32_t bytes, uint32_t mbar) {
    asm volatile("cp.async.bulk.shared::cluster.global.mbarrier::complete_tx::bytes "
                 "[%0], [%1], %2, [%3];"
                 :: "r"(dst), "l"(src), "r"(bytes), "r"(mbar) : "memory");
}
__device__ __forceinline__ void mbar_wait(uint32_t a, uint32_t parity) {
    asm volatile(
        "{\n\t.reg .pred P;\n\t"
        "WL_%=:\n\t"
        "mbarrier.try_wait.parity.shared.b64 P, [%0], %1, 0x989680;\n\t"
        "@P bra.uni WD_%=;\n\t"
        "bra.uni WL_%=;\n\t"
        "WD_%=:\n\t}"
        :: "r"(a), "r"(parity) : "memory");
}
__device__ __forceinline__ uint32_t s2u(const void* p) {
    uint32_t a;
    asm("{ .reg .u64 t; cvta.to.shared.u64 t, %1; cvt.u32.u64 %0, t; }"
        : "=r"(a) : "l"(p));
    return a;
}

__global__ __launch_bounds__(NTHREADS, 1)
void rotary_kernel(const float* __restrict__ xq,
                   const float* __restrict__ xk,
                   const float* __restrict__ rot,
                   float* __restrict__ out) {
    extern __shared__ char smem[];
    const uint32_t sbase = s2u(smem);
    const int s   = blockIdx.x;
    const int tid = threadIdx.x;
    const int g   = tid >> 5;     // warp-group 0..7 (one warp each)
    const int t   = tid & 31;     // 4-col slot 0..31

    // ---- Init stage mbarriers, then fire the 4 bulk copies ----
    if (tid == 0) {
        #pragma unroll
        for (int st = 0; st < NSTAGES; st++)
            mbar_init(sbase + SM_MBAR + st * 8, 1);
    }
    __syncthreads();
    if (tid == 0) {
        const char* Rg = (const char*)rot + (size_t)s * HEAD_DIM * HEAD_DIM * 4;
        #pragma unroll
        for (int st = 0; st < NSTAGES; st++) {
            mbar_expect_tx(sbase + SM_MBAR + st * 8, STAGE_BYTES);
            bulk_g2s(sbase + SM_R + st * STAGE_BYTES,
                     Rg + (size_t)st * STAGE_BYTES,
                     STAGE_BYTES, sbase + SM_MBAR + st * 8);
        }
    }

    // ---- Stage x rows (LDG float4, overlaps TMA), duplicated float2 ----
    float2* xs2 = (float2*)(smem + SM_X);       // [9][128]
    for (int idx = tid; idx < NROWS * (HEAD_DIM / 4); idx += NTHREADS) {
        const int n = idx >> 5;
        const int c = idx & 31;
        const float4 v = (n < NQ)
            ? *(const float4*)(xq + ((size_t)(n * SEQ_LEN + s) * HEAD_DIM) + c * 4)
            : *(const float4*)(xk + ((size_t)s * HEAD_DIM) + c * 4);
        xs2[n * HEAD_DIM + c * 4 + 0] = make_float2(v.x, v.x);
        xs2[n * HEAD_DIM + c * 4 + 1] = make_float2(v.y, v.y);
        xs2[n * HEAD_DIM + c * 4 + 2] = make_float2(v.z, v.z);
        xs2[n * HEAD_DIM + c * 4 + 3] = make_float2(v.w, v.w);
    }
    __syncthreads();

    // ---- Wait for this group's R stage, then accumulate ----
    mbar_wait(sbase + SM_MBAR + (g >> 1) * 8, 0);

    unsigned long long acc01[NROWS], acc23[NROWS];
    #pragma unroll
    for (int n = 0; n < NROWS; n++) { acc01[n] = 0ull; acc23[n] = 0ull; }

    const float4* Rsm = (const float4*)(smem + SM_R);   // [128][32]
    #pragma unroll
    for (int h = 0; h < HCHUNK; h++) {
        const int hh = g * HCHUNK + h;
        const float4 r = Rsm[hh * (HEAD_DIM / 4) + t];  // LDS.128, conflict-free
        unsigned long long r01, r23;
        asm("mov.b64 %0, {%1, %2};" : "=l"(r01) : "f"(r.x), "f"(r.y));
        asm("mov.b64 %0, {%1, %2};" : "=l"(r23) : "f"(r.z), "f"(r.w));
        #pragma unroll
        for (int n = 0; n < NROWS; n++) {
            const unsigned long long x2 =
                *(const unsigned long long*)&xs2[n * HEAD_DIM + hh];  // LDS.64 bcast
            asm("fma.rn.f32x2 %0, %1, %2, %0;" : "+l"(acc01[n]) : "l"(x2), "l"(r01));
            asm("fma.rn.f32x2 %0, %1, %2, %0;" : "+l"(acc23[n]) : "l"(x2), "l"(r23));
        }
    }

    // ---- Write partials (STS.128) ----
    float* part = (float*)(smem + SM_PART);     // [8][9][128]
    #pragma unroll
    for (int n = 0; n < NROWS; n++) {
        float a0, a1, a2, a3;
        asm("mov.b64 {%0, %1}, %2;" : "=f"(a0), "=f"(a1) : "l"(acc01[n]));
        asm("mov.b64 {%0, %1}, %2;" : "=f"(a2), "=f"(a3) : "l"(acc23[n]));
        *(float4*)&part[(g * NROWS + n) * HEAD_DIM + t * 4] =
            make_float4(a0, a1, a2, a3);
    }
    __syncthreads();

    // ---- Reduce 8 partials: 9 rows x 32 float4-chunks = 288 outputs ----
    for (int idx = tid; idx < NROWS * (HEAD_DIM / 4); idx += NTHREADS) {
        const int n = idx >> 5;
        const int c = idx & 31;
        float4 v = make_float4(0.f, 0.f, 0.f, 0.f);
        #pragma unroll
        for (int gg = 0; gg < NGROUPS; gg++) {
            const float4 p = *(const float4*)&part[(gg * NROWS + n) * HEAD_DIM + c * 4];
            v.x += p.x; v.y += p.y; v.z += p.z; v.w += p.w;
        }
        // n==8 lands exactly at the xk output block (uniform indexing).
        const size_t o = (size_t)(n * SEQ_LEN + s) * HEAD_DIM + c * 4;
        *(float4*)(out + o) = v;
    }
}

extern "C" void kernel_launch(void* const* d_in, const int* in_sizes, int n_in,
                              void* d_out, int out_size) {
    const float* xq  = (const float*)d_in[0];
    const float* xk  = (const float*)d_in[1];
    const float* rot = (const float*)d_in[2];
    float* out = (float*)d_out;

    cudaFuncSetAttribute(rotary_kernel,
                         cudaFuncAttributeMaxDynamicSharedMemorySize, SM_TOTAL);
    rotary_kernel<<<SEQ_LEN, NTHREADS, SM_TOTAL>>>(xq, xk, rot, out);
}

// round 9
// speedup vs baseline: 1.2903x; 1.1843x over previous
#include <cuda_runtime.h>
#include <cstdint>

// TtLlamaRotary: out[n,s,:] = x[n,s,:] @ R[s,:,:]
//   xq [8,128,128], xk [1,128,128], rot [128,128,128], out concat (9,128,128)
//
// One CTA per seq position s (grid 128, block 512 = 16 h-groups x 32 threads).
// Thread owns 4 output columns; full 128-d width per CTA so x is staged ONCE
// (minimum-traffic design: rot+x+out read/written exactly once = 9.57 MB).
// R slice (8 x float4) prefetched into registers before the x-staging barrier
// so both DRAM round trips overlap. Packed fma.rn.f32x2 accumulation,
// 16-way smem partials, float4 stores.

#define SEQ_LEN 128
#define HEAD_DIM 128
#define NQ 8
#define NROWS 9
#define TPG 32                        // threads per h-group (4 cols each)
#define NGROUPS 16
#define HCHUNK 8                      // 128 / 16
#define NTHREADS 512

// dynamic smem layout (bytes)
#define SM_X     0                           // 9*128*8 = 9216 (dup float2)
#define SM_PART  9216                        // 16*9*128*4 = 73728
#define SM_TOTAL (SM_PART + 73728)           // 82944

__global__ __launch_bounds__(NTHREADS, 1)
void rotary_kernel(const float* __restrict__ xq,
                   const float* __restrict__ xk,
                   const float* __restrict__ rot,
                   float* __restrict__ out) {
    extern __shared__ char smem[];
    float2* xs2  = (float2*)(smem + SM_X);      // [9][128] duplicated
    float*  part = (float*)(smem + SM_PART);    // [16][9][128]

    const int s   = blockIdx.x;
    const int tid = threadIdx.x;
    const int g   = tid / TPG;        // h-group 0..15
    const int t   = tid % TPG;        // 4-col slot 0..31

    // ---- Prefetch R slice into registers (overlaps x staging) ----
    const float4* __restrict__ R4 =
        (const float4*)rot + (size_t)s * (HEAD_DIM * HEAD_DIM / 4) + t;
    float4 rv[HCHUNK];
    #pragma unroll
    for (int h = 0; h < HCHUNK; h++)
        rv[h] = R4[(size_t)(g * HCHUNK + h) * (HEAD_DIM / 4)];

    // ---- Stage x rows ONCE (float4 loads), duplicated float2 ----
    // 9 rows x 32 float4 = 288 chunks; threads 288..511 skip.
    if (tid < NROWS * (HEAD_DIM / 4)) {
        const int n = tid >> 5;       // row 0..8
        const int c = tid & 31;       // float4 chunk
        const float4 v = (n < NQ)
            ? *(const float4*)(xq + ((size_t)(n * SEQ_LEN + s) * HEAD_DIM) + c * 4)
            : *(const float4*)(xk + ((size_t)s * HEAD_DIM) + c * 4);
        xs2[n * HEAD_DIM + c * 4 + 0] = make_float2(v.x, v.x);
        xs2[n * HEAD_DIM + c * 4 + 1] = make_float2(v.y, v.y);
        xs2[n * HEAD_DIM + c * 4 + 2] = make_float2(v.z, v.z);
        xs2[n * HEAD_DIM + c * 4 + 3] = make_float2(v.w, v.w);
    }
    __syncthreads();

    // ---- Accumulate: 8 h-steps x 9 rows, packed f32x2 ----
    unsigned long long acc01[NROWS], acc23[NROWS];
    #pragma unroll
    for (int n = 0; n < NROWS; n++) { acc01[n] = 0ull; acc23[n] = 0ull; }

    #pragma unroll
    for (int h = 0; h < HCHUNK; h++) {
        const int hh = g * HCHUNK + h;
        unsigned long long r01, r23;
        asm("mov.b64 %0, {%1, %2};" : "=l"(r01) : "f"(rv[h].x), "f"(rv[h].y));
        asm("mov.b64 %0, {%1, %2};" : "=l"(r23) : "f"(rv[h].z), "f"(rv[h].w));
        #pragma unroll
        for (int n = 0; n < NROWS; n++) {
            const unsigned long long x2 =
                *(const unsigned long long*)&xs2[n * HEAD_DIM + hh];  // LDS.64 bcast
            asm("fma.rn.f32x2 %0, %1, %2, %0;" : "+l"(acc01[n]) : "l"(x2), "l"(r01));
            asm("fma.rn.f32x2 %0, %1, %2, %0;" : "+l"(acc23[n]) : "l"(x2), "l"(r23));
        }
    }

    // ---- Write partials (STS.128) ----
    #pragma unroll
    for (int n = 0; n < NROWS; n++) {
        float a0, a1, a2, a3;
        asm("mov.b64 {%0, %1}, %2;" : "=f"(a0), "=f"(a1) : "l"(acc01[n]));
        asm("mov.b64 {%0, %1}, %2;" : "=f"(a2), "=f"(a3) : "l"(acc23[n]));
        *(float4*)&part[(g * NROWS + n) * HEAD_DIM + t * 4] =
            make_float4(a0, a1, a2, a3);
    }
    __syncthreads();

    // ---- Reduce 16 partials: 9 rows x 32 float4-chunks = 288 outputs ----
    if (tid < NROWS * (HEAD_DIM / 4)) {
        const int n = tid >> 5;
        const int c = tid & 31;
        float4 v = make_float4(0.f, 0.f, 0.f, 0.f);
        #pragma unroll
        for (int gg = 0; gg < NGROUPS; gg++) {
            const float4 p =
                *(const float4*)&part[(gg * NROWS + n) * HEAD_DIM + c * 4];
            v.x += p.x; v.y += p.y; v.z += p.z; v.w += p.w;
        }
        // n==8 lands exactly at the xk output block (uniform indexing).
        const size_t o = (size_t)(n * SEQ_LEN + s) * HEAD_DIM + c * 4;
        *(float4*)(out + o) = v;
    }
}

extern "C" void kernel_launch(void* const* d_in, const int* in_sizes, int n_in,
                              void* d_out, int out_size) {
    const float* xq  = (const float*)d_in[0];
    const float* xk  = (const float*)d_in[1];
    const float* rot = (const float*)d_in[2];
    float* out = (float*)d_out;

    cudaFuncSetAttribute(rotary_kernel,
                         cudaFuncAttributeMaxDynamicSharedMemorySize, SM_TOTAL);
    rotary_kernel<<<SEQ_LEN, NTHREADS, SM_TOTAL>>>(xq, xk, rot, out);
}